// round 5
// baseline (speedup 1.0000x reference)
#include <cuda_runtime.h>
#include <math.h>

static constexpr int NB = 128;     // batch
static constexpr int SL = 256;     // seq len
static constexpr int QL = 8;       // query len
static constexpr int ED = 300;     // embed dim
static constexpr int HD = 300;     // hidden dim
static constexpr int GW = 1200;    // 4*HD gate width
static constexpr int MS = NB * SL; // 32768
static constexpr int MQ = NB * QL; // 1024
static constexpr float EPSN = 1e-12f;

// ---------------- static device scratch (no runtime allocation) ----------------
__device__ float d_Gf[MS * GW];        // input-proj gates, seqs forward  (incl. biases)
__device__ float d_Gb[MS * GW];        // seqs backward
__device__ float d_Gqf[MQ * GW];       // queries forward
__device__ float d_Gqb[MQ * GW];       // queries backward
__device__ float d_Hcat[MS * 2 * HD];  // [N, L, 2H] concat(hf, hb)
__device__ float d_HcatQ[MQ * 2 * HD];
__device__ float d_h[2 * 2 * NB * HD]; // [dir][parity][N*H] ping-pong hidden
__device__ float d_c[2 * NB * HD];     // [dir][N*H] cell (seqs)
__device__ float d_hq[2 * 2 * NB * HD];
__device__ float d_cq[2 * NB * HD];    // cell (queries)
__device__ float d_hs[MS * HD];        // encoded seq states
__device__ float d_qenc[MQ * HD];      // encoded query states
__device__ float d_tmp[MS * HD];       // tanh(hs@Wa^T+ba); later reused as P = hs@Wf
__device__ float d_tmpq[MQ * HD];
__device__ float d_s[MS];              // attention logits (seqs)
__device__ float d_sq[MQ];             // attention logits (queries)
__device__ float d_qv[NB * HD];        // pooled query vec
__device__ float d_qp[NB * HD];        // qv @ Wf
__device__ float d_qn[NB * HD];        // normalized

// ---------------- init ----------------
__global__ void init_state() {
    int i = blockIdx.x * blockDim.x + threadIdx.x;
    if (i < 2 * 2 * NB * HD) { d_h[i] = 0.f; d_hq[i] = 0.f; }
    if (i < 2 * NB * HD)     { d_c[i] = 0.f; d_cq[i] = 0.f; }
}

// ---------------- gathered input-projection GEMM ----------------
// G[m, j] = sum_e emb[tok[m], e] * W[j, e] + b1[j] + b2[j]    (M x 1200, K=300)
__global__ void proj_gemm(const int* __restrict__ tok, const float* __restrict__ emb,
                          const float* __restrict__ W, const float* __restrict__ b1,
                          const float* __restrict__ b2, float* __restrict__ G, int M) {
    __shared__ __align__(16) float As[8][128];
    __shared__ __align__(16) float Bs[8][128];
    int tid = threadIdx.x;
    int m0 = blockIdx.y * 128, n0 = blockIdx.x * 128;
    int tx = tid % 16, ty = tid / 16;
    int am = tid >> 1, akq = (tid & 1) * 4;
    int arow = m0 + am;
    const float* aptr = emb + (long)((arow < M) ? tok[arow] : 0) * ED;
    int bcol = n0 + am;
    float acc[8][8];
#pragma unroll
    for (int i = 0; i < 8; i++)
#pragma unroll
        for (int j = 0; j < 8; j++) acc[i][j] = 0.f;

    for (int k0 = 0; k0 < ED; k0 += 8) {
#pragma unroll
        for (int j = 0; j < 4; j++) {
            int kk = k0 + akq + j;
            As[akq + j][am] = (arow < M && kk < ED) ? aptr[kk] : 0.f;
            Bs[akq + j][am] = (bcol < GW && kk < ED) ? W[bcol * ED + kk] : 0.f;
        }
        __syncthreads();
#pragma unroll
        for (int k = 0; k < 8; k++) {
            float4 a0 = *(const float4*)&As[k][ty * 8];
            float4 a1 = *(const float4*)&As[k][ty * 8 + 4];
            float4 c0 = *(const float4*)&Bs[k][tx * 8];
            float4 c1 = *(const float4*)&Bs[k][tx * 8 + 4];
            float av8[8] = {a0.x, a0.y, a0.z, a0.w, a1.x, a1.y, a1.z, a1.w};
            float bv8[8] = {c0.x, c0.y, c0.z, c0.w, c1.x, c1.y, c1.z, c1.w};
#pragma unroll
            for (int i = 0; i < 8; i++)
#pragma unroll
                for (int j = 0; j < 8; j++) acc[i][j] += av8[i] * bv8[j];
        }
        __syncthreads();
    }
#pragma unroll
    for (int i = 0; i < 8; i++) {
        int row = m0 + ty * 8 + i;
        if (row < M) {
#pragma unroll
            for (int j = 0; j < 8; j++) {
                int col = n0 + tx * 8 + j;
                if (col < GW) G[(long)row * GW + col] = acc[i][j] + b1[col] + b2[col];
            }
        }
    }
}

// ---------------- generic SGEMM: C = A @ op(B) (+bias) (+tanh) ----------------
__global__ void gemm_k(const float* __restrict__ A, const float* __restrict__ B,
                       const float* __restrict__ bias, float* __restrict__ C,
                       int M, int N, int K, int transB, int act) {
    __shared__ __align__(16) float As[8][128];
    __shared__ __align__(16) float Bs[8][128];
    int tid = threadIdx.x;
    int m0 = blockIdx.y * 128, n0 = blockIdx.x * 128;
    int tx = tid % 16, ty = tid / 16;
    int am = tid >> 1, akq = (tid & 1) * 4;
    int arow = m0 + am;
    int bcol = n0 + am;
    float acc[8][8];
#pragma unroll
    for (int i = 0; i < 8; i++)
#pragma unroll
        for (int j = 0; j < 8; j++) acc[i][j] = 0.f;

    for (int k0 = 0; k0 < K; k0 += 8) {
#pragma unroll
        for (int j = 0; j < 4; j++) {
            int kk = k0 + akq + j;
            As[akq + j][am] = (arow < M && kk < K) ? A[(long)arow * K + kk] : 0.f;
        }
        if (transB) {
#pragma unroll
            for (int j = 0; j < 4; j++) {
                int kk = k0 + akq + j;
                Bs[akq + j][am] = (bcol < N && kk < K) ? B[(long)bcol * K + kk] : 0.f;
            }
        } else {
            for (int i = tid; i < 1024; i += 256) {
                int k = i >> 7, j = i & 127;
                Bs[k][j] = (k0 + k < K && n0 + j < N) ? B[(long)(k0 + k) * N + n0 + j] : 0.f;
            }
        }
        __syncthreads();
#pragma unroll
        for (int k = 0; k < 8; k++) {
            float4 a0 = *(const float4*)&As[k][ty * 8];
            float4 a1 = *(const float4*)&As[k][ty * 8 + 4];
            float4 c0 = *(const float4*)&Bs[k][tx * 8];
            float4 c1 = *(const float4*)&Bs[k][tx * 8 + 4];
            float av8[8] = {a0.x, a0.y, a0.z, a0.w, a1.x, a1.y, a1.z, a1.w};
            float bv8[8] = {c0.x, c0.y, c0.z, c0.w, c1.x, c1.y, c1.z, c1.w};
#pragma unroll
            for (int i = 0; i < 8; i++)
#pragma unroll
                for (int j = 0; j < 8; j++) acc[i][j] += av8[i] * bv8[j];
        }
        __syncthreads();
    }
#pragma unroll
    for (int i = 0; i < 8; i++) {
        int row = m0 + ty * 8 + i;
        if (row < M) {
#pragma unroll
            for (int j = 0; j < 8; j++) {
                int col = n0 + tx * 8 + j;
                if (col < N) {
                    float v = acc[i][j] + (bias ? bias[col] : 0.f);
                    if (act) v = tanhf(v);
                    C[(long)row * N + col] = v;
                }
            }
        }
    }
}

// ---------------- fused LSTM recurrence step (one launch per timestep) ----------------
// grid (10 unit-blocks, 16 row-blocks, 2 dirs) = 320 CTAs x 128 threads.
// CTA = (4 gates x 32 units) x 8 batch rows. Thread = 8 gate-cols x 1 row:
// per k, 8 FFMA vs 2 LDS.128 + 1 broadcast LDS.32 -> FFMA-dominant.
// Whh streamed in 12-deep k panels (12 | 300); h rows staged in smem per step.
// Cross-launch h/c via plain ld/st: L1 is flushed at launch boundaries.
__device__ __forceinline__ float sigm(float x) { return 1.f / (1.f + expf(-x)); }

__global__ void __launch_bounds__(128)
lstm_step(const float* __restrict__ WhhF, const float* __restrict__ WhhB,
          int t, int Lcur, int isq) {
    const int tid = threadIdx.x;            // 128
    const int tx = tid & 15, ty = tid >> 4; // 16 col-groups x 8 rows
    const int ub = blockIdx.x, rbk = blockIdx.y, dir = blockIdx.z;
    const int u0 = ub * 32, n0 = rbk * 8;

    const float* __restrict__ Whh = dir ? WhhB : WhhF;
    const float* __restrict__ G = isq ? (dir ? d_Gqb : d_Gqf)
                                      : (dir ? d_Gb : d_Gf);
    float* hbase = isq ? d_hq : d_h;
    float* cbuf = (isq ? d_cq : d_c) + dir * (NB * HD);
    const float* hp = hbase + (dir * 2 + (t & 1)) * (NB * HD);
    float* hn = hbase + (dir * 2 + ((t + 1) & 1)) * (NB * HD);
    float* Hc = isq ? d_HcatQ : d_Hcat;
    const int tpos = dir ? (Lcur - 1 - t) : t;

    __shared__ __align__(16) float h_s[8][304];   // 8 rows of h_prev
    __shared__ __align__(16) float Ws[12][128];   // k-panel of Whh (gate-col major)
    __shared__ float gs[8][128];                  // staged gates for cell update

    // stage h_prev rows (8 x 300 = 600 float4)
    for (int i = tid; i < 600; i += 128) {
        int r = i / 75, q = i - r * 75;
        float4 v = *((const float4*)(hp + (size_t)(n0 + r) * HD) + q);
        *((float4*)&h_s[r][0] + q) = v;
    }

    // init accumulators with input-proj gates (include biases)
    float acc[8];
    const int gate = tx >> 2;
    const int ulb = (tx & 3) * 8;  // unit-lane base of this thread's 8 cols
    {
        const float* gp = G + ((size_t)(n0 + ty) * Lcur + tpos) * GW + gate * HD;
#pragma unroll
        for (int j = 0; j < 8; j++) {
            int u = u0 + ulb + j;
            acc[j] = (u < HD) ? gp[u] : 0.f;
        }
    }

    // Whh panel loader mapping: col lc -> gate (lc>>5), unit u0+(lc&31)
    const int lc = tid;
    const int lw = (lc >> 5) * HD + u0 + (lc & 31);
    const bool lval = (u0 + (lc & 31)) < HD;

    for (int k0 = 0; k0 < HD; k0 += 12) {
        __syncthreads();  // WAR on Ws (also covers h_s visibility on first iter)
        if (lval) {
            const float* src = Whh + (size_t)lw * HD + k0;
#pragma unroll
            for (int q = 0; q < 3; q++) {
                float4 v = *((const float4*)src + q);
                Ws[q * 4 + 0][lc] = v.x;
                Ws[q * 4 + 1][lc] = v.y;
                Ws[q * 4 + 2][lc] = v.z;
                Ws[q * 4 + 3][lc] = v.w;
            }
        } else {
#pragma unroll
            for (int kk = 0; kk < 12; kk++) Ws[kk][lc] = 0.f;
        }
        __syncthreads();
#pragma unroll
        for (int kk = 0; kk < 12; kk++) {
            float a = h_s[ty][k0 + kk];
            float4 b0 = *(const float4*)&Ws[kk][tx * 8];
            float4 b1 = *(const float4*)&Ws[kk][tx * 8 + 4];
            acc[0] += a * b0.x; acc[1] += a * b0.y;
            acc[2] += a * b0.z; acc[3] += a * b0.w;
            acc[4] += a * b1.x; acc[5] += a * b1.y;
            acc[6] += a * b1.z; acc[7] += a * b1.w;
        }
    }

    // stage gates for regrouping (thread has 8 cols of ONE gate)
#pragma unroll
    for (int j = 0; j < 8; j++) gs[ty][tx * 8 + j] = acc[j];
    __syncthreads();

    // cell update: 2 (unit,row) pairs per thread; all 4 gates from gs
    for (int p = tid; p < 256; p += 128) {
        int ul = p & 31, r = p >> 5;
        int u = u0 + ul;
        if (u < HD) {
            int n = n0 + r;
            float gi = gs[r][ul];
            float gf = gs[r][32 + ul];
            float gg = gs[r][64 + ul];
            float go = gs[r][96 + ul];
            float cold = cbuf[n * HD + u];
            float cn = sigm(gf) * cold + sigm(gi) * tanhf(gg);
            float hv = sigm(go) * tanhf(cn);
            cbuf[n * HD + u] = cn;
            hn[n * HD + u] = hv;
            Hc[((size_t)n * Lcur + tpos) * (2 * HD) + dir * HD + u] = hv;
        }
    }
}

// ---------------- attention dot: s[m] = dot(X[m,:], av) ----------------
__global__ void att_dot(const float* __restrict__ X, const float* __restrict__ av,
                        float* __restrict__ out, int M) {
    int w = (blockIdx.x * blockDim.x + threadIdx.x) >> 5;
    int lane = threadIdx.x & 31;
    if (w >= M) return;
    const float* x = X + (long)w * HD;
    float a = 0.f;
    for (int d = lane; d < HD; d += 32) a += x[d] * av[d];
#pragma unroll
    for (int o = 16; o; o >>= 1) a += __shfl_down_sync(0xffffffffu, a, o);
    if (lane == 0) out[w] = a;
}

// ---------------- query softmax pool ----------------
__global__ void qpool_k() {
    int n = blockIdx.x, tid = threadIdx.x;  // 128 threads
    __shared__ float sc[QL];
    if (tid < QL) sc[tid] = d_sq[n * QL + tid];
    __syncthreads();
    float mx = -1e30f;
#pragma unroll
    for (int l = 0; l < QL; l++) mx = fmaxf(mx, sc[l]);
    float e[QL], sum = 0.f;
#pragma unroll
    for (int l = 0; l < QL; l++) { e[l] = expf(sc[l] - mx); sum += e[l]; }
    float inv = 1.f / sum;
    for (int d = tid; d < HD; d += 128) {
        float a = 0.f;
#pragma unroll
        for (int l = 0; l < QL; l++) a += e[l] * d_qenc[(n * QL + l) * HD + d];
        d_qv[n * HD + d] = a * inv;
    }
}

// ---------------- normalize query: qn = qp / max(||qp||, eps) ----------------
__global__ void qnorm_k() {
    int n = blockIdx.x, tid = threadIdx.x;  // 128 threads
    __shared__ float red[128];
    float ss = 0.f;
    for (int d = tid; d < HD; d += 128) { float v = d_qp[n * HD + d]; ss += v * v; }
    red[tid] = ss;
    __syncthreads();
    for (int s = 64; s; s >>= 1) { if (tid < s) red[tid] += red[tid + s]; __syncthreads(); }
    float inv = 1.f / fmaxf(sqrtf(red[0]), EPSN);
    for (int d = tid; d < HD; d += 128) d_qn[n * HD + d] = d_qp[n * HD + d] * inv;
}

// ---------------- final: sliding-window combos + cosines + mix ----------------
__global__ void final_k(const float* __restrict__ sw, const float* __restrict__ P,
                        float* __restrict__ out) {
    int w = (blockIdx.x * blockDim.x + threadIdx.x) >> 5;
    int lane = threadIdx.x & 31;
    if (w >= MS) return;
    int n = w >> 8, l = w & 255;
    int ln = (l + 1 < SL) ? l + 1 : SL - 1;
    int lp = (l > 0) ? l - 1 : 0;
    float sl = d_s[n * SL + l];
    float sn = d_s[n * SL + ln];
    float sp = d_s[n * SL + lp];
    float m1 = fmaxf(sl, sn);
    float e0 = expf(sl - m1), e1 = expf(sn - m1);
    float wf0 = e0 / (e0 + e1), wf1 = 1.f - wf0;
    float m2 = fmaxf(sp, sl);
    float f0 = expf(sp - m2), f1 = expf(sl - m2);
    float wb0 = f0 / (f0 + f1), wb1 = 1.f - wb0;

    const float* Pl = P + (long)(n * SL + l) * HD;
    const float* Pn = P + (long)(n * SL + ln) * HD;
    const float* Pp = P + (long)(n * SL + lp) * HD;
    const float* q = d_qn + n * HD;

    float dpq = 0.f, dpp = 0.f, duq = 0.f, duu = 0.f, dvq = 0.f, dvv = 0.f;
    for (int d = lane; d < HD; d += 32) {
        float p = Pl[d], pn = Pn[d], pp = Pp[d], qd = q[d];
        float u = wf0 * p + wf1 * pn;
        float v = wb0 * pp + wb1 * p;
        dpq += p * qd; dpp += p * p;
        duq += u * qd; duu += u * u;
        dvq += v * qd; dvv += v * v;
    }
#pragma unroll
    for (int o = 16; o; o >>= 1) {
        dpq += __shfl_down_sync(0xffffffffu, dpq, o);
        dpp += __shfl_down_sync(0xffffffffu, dpp, o);
        duq += __shfl_down_sync(0xffffffffu, duq, o);
        duu += __shfl_down_sync(0xffffffffu, duu, o);
        dvq += __shfl_down_sync(0xffffffffu, dvq, o);
        dvv += __shfl_down_sync(0xffffffffu, dvv, o);
    }
    if (lane == 0) {
        float c1 = dpq / fmaxf(sqrtf(dpp), EPSN);
        float c2 = duq / fmaxf(sqrtf(duu), EPSN);
        float c3 = dvq / fmaxf(sqrtf(dvv), EPSN);
        out[w] = c1 * sw[0] + c2 * sw[1] + c3 * sw[2];
    }
}

// ---------------- launch ----------------
extern "C" void kernel_launch(void* const* d_in, const int* in_sizes, int n_in,
                              void* d_out, int out_size) {
    const int*   seqs = (const int*)d_in[0];
    const int*   quer = (const int*)d_in[1];
    const float* emb  = (const float*)d_in[2];
    const float* WihF = (const float*)d_in[3];
    const float* WhhF = (const float*)d_in[4];
    const float* bihF = (const float*)d_in[5];
    const float* bhhF = (const float*)d_in[6];
    const float* WihB = (const float*)d_in[7];
    const float* WhhB = (const float*)d_in[8];
    const float* bihB = (const float*)d_in[9];
    const float* bhhB = (const float*)d_in[10];
    const float* Wc   = (const float*)d_in[11];
    const float* bc   = (const float*)d_in[12];
    const float* Wa   = (const float*)d_in[13];
    const float* ba   = (const float*)d_in[14];
    const float* av   = (const float*)d_in[15];
    const float* Wf   = (const float*)d_in[16];
    const float* sw   = (const float*)d_in[17];

    void* p;
    cudaGetSymbolAddress(&p, d_Gf);    float* pGf    = (float*)p;
    cudaGetSymbolAddress(&p, d_Gb);    float* pGb    = (float*)p;
    cudaGetSymbolAddress(&p, d_Gqf);   float* pGqf   = (float*)p;
    cudaGetSymbolAddress(&p, d_Gqb);   float* pGqb   = (float*)p;
    cudaGetSymbolAddress(&p, d_Hcat);  float* pHcat  = (float*)p;
    cudaGetSymbolAddress(&p, d_HcatQ); float* pHcatQ = (float*)p;
    cudaGetSymbolAddress(&p, d_hs);    float* phs    = (float*)p;
    cudaGetSymbolAddress(&p, d_qenc);  float* pqenc  = (float*)p;
    cudaGetSymbolAddress(&p, d_tmp);   float* ptmp   = (float*)p;  // doubles as P
    cudaGetSymbolAddress(&p, d_tmpq);  float* ptmpq  = (float*)p;
    cudaGetSymbolAddress(&p, d_s);     float* ps     = (float*)p;
    cudaGetSymbolAddress(&p, d_sq);    float* psq    = (float*)p;
    cudaGetSymbolAddress(&p, d_qv);    float* pqv    = (float*)p;
    cudaGetSymbolAddress(&p, d_qp);    float* pqp    = (float*)p;

    init_state<<<600, 256>>>();

    // input projections (gather + GEMM + both biases)
    dim3 gp(10, 256);
    proj_gemm<<<gp, 256>>>(seqs, emb, WihF, bihF, bhhF, pGf, MS);
    proj_gemm<<<gp, 256>>>(seqs, emb, WihB, bihB, bhhB, pGb, MS);
    dim3 gpq(10, 8);
    proj_gemm<<<gpq, 256>>>(quer, emb, WihF, bihF, bhhF, pGqf, MQ);
    proj_gemm<<<gpq, 256>>>(quer, emb, WihB, bihB, bhhB, pGqb, MQ);

    // recurrences: one launch per timestep, both dirs (proven-safe structure)
    dim3 gl(10, 16, 2);
    for (int t = 0; t < SL; t++) lstm_step<<<gl, 128>>>(WhhF, WhhB, t, SL, 0);
    for (int t = 0; t < QL; t++) lstm_step<<<gl, 128>>>(WhhF, WhhB, t, QL, 1);

    // combine directions: hs = Hcat @ Wc^T + bc
    gemm_k<<<dim3(3, 256), 256>>>(pHcat, Wc, bc, phs, MS, HD, 2 * HD, 1, 0);
    gemm_k<<<dim3(3, 8), 256>>>(pHcatQ, Wc, bc, pqenc, MQ, HD, 2 * HD, 1, 0);

    // attention logits: tanh(X @ Wa^T + ba) . att_vec
    gemm_k<<<dim3(3, 256), 256>>>(phs, Wa, ba, ptmp, MS, HD, HD, 1, 1);
    gemm_k<<<dim3(3, 8), 256>>>(pqenc, Wa, ba, ptmpq, MQ, HD, HD, 1, 1);
    att_dot<<<MS / 8, 256>>>(ptmp, av, ps, MS);
    att_dot<<<MQ / 8, 256>>>(ptmpq, av, psq, MQ);

    // pooled, projected, normalized query
    qpool_k<<<NB, 128>>>();
    gemm_k<<<dim3(3, 1), 256>>>(pqv, Wf, nullptr, pqp, NB, HD, HD, 0, 0);
    qnorm_k<<<NB, 128>>>();

    // P = hs @ Wf  (fwd/bwd combos are linear in hs, so one projection suffices)
    gemm_k<<<dim3(3, 256), 256>>>(phs, Wf, nullptr, ptmp, MS, HD, HD, 0, 0);

    final_k<<<MS / 8, 256>>>(sw, ptmp, (float*)d_out);
}

// round 6
// speedup vs baseline: 1.6355x; 1.6355x over previous
#include <cuda_runtime.h>
#include <math.h>

static constexpr int NB = 128;     // batch
static constexpr int SL = 256;     // seq len
static constexpr int QL = 8;       // query len
static constexpr int ED = 300;     // embed dim
static constexpr int HD = 300;     // hidden dim
static constexpr int GW = 1200;    // 4*HD gate width
static constexpr int MS = NB * SL; // 32768
static constexpr int MQ = NB * QL; // 1024
static constexpr float EPSN = 1e-12f;

// ---------------- static device scratch (no runtime allocation) ----------------
__device__ float d_Gf[MS * GW];        // input-proj gates, seqs forward  (incl. biases)
__device__ float d_Gb[MS * GW];        // seqs backward
__device__ float d_Gqf[MQ * GW];       // queries forward
__device__ float d_Gqb[MQ * GW];       // queries backward
__device__ float d_Hcat[MS * 2 * HD];  // [N, L, 2H] concat(hf, hb)
__device__ float d_HcatQ[MQ * 2 * HD];
__device__ float d_h[2 * 2 * NB * HD]; // [dir][parity][N*H] ping-pong hidden
__device__ float d_c[2 * NB * HD];     // [dir][N*H] cell (seqs)
__device__ float d_hq[2 * 2 * NB * HD];
__device__ float d_cq[2 * NB * HD];    // cell (queries)
__device__ float d_hs[MS * HD];        // encoded seq states
__device__ float d_qenc[MQ * HD];      // encoded query states
__device__ float d_tmp[MS * HD];       // tanh(hs@Wa^T+ba); later reused as P = hs@Wf
__device__ float d_tmpq[MQ * HD];
__device__ float d_s[MS];              // attention logits (seqs)
__device__ float d_sq[MQ];             // attention logits (queries)
__device__ float d_qv[NB * HD];        // pooled query vec
__device__ float d_qp[NB * HD];        // qv @ Wf
__device__ float d_qn[NB * HD];        // normalized

// ---------------- init ----------------
__global__ void init_state() {
    int i = blockIdx.x * blockDim.x + threadIdx.x;
    if (i < 2 * 2 * NB * HD) { d_h[i] = 0.f; d_hq[i] = 0.f; }
    if (i < 2 * NB * HD)     { d_c[i] = 0.f; d_cq[i] = 0.f; }
}

// ---------------- gathered input-projection GEMM (double-buffered) ----------------
// G[m, j] = sum_e emb[tok[m], e] * W[j, e] + b1[j] + b2[j]    (M x 1200, K=300)
__global__ void __launch_bounds__(256)
proj_gemm(const int* __restrict__ tok, const float* __restrict__ emb,
          const float* __restrict__ W, const float* __restrict__ b1,
          const float* __restrict__ b2, float* __restrict__ G, int M) {
    __shared__ __align__(16) float As[2][8][128];
    __shared__ __align__(16) float Bs[2][8][128];
    int tid = threadIdx.x;
    int m0 = blockIdx.y * 128, n0 = blockIdx.x * 128;
    int tx = tid % 16, ty = tid / 16;
    int am = tid >> 1, akq = (tid & 1) * 4;
    int arow = m0 + am;
    const float* aptr = emb + (size_t)((arow < M) ? tok[arow] : 0) * ED;
    int bcol = n0 + am;
    float acc[8][8];
#pragma unroll
    for (int i = 0; i < 8; i++)
#pragma unroll
        for (int j = 0; j < 8; j++) acc[i][j] = 0.f;

    float ra[4], rbv[4];
    const int nP = (ED + 7) / 8;  // 38

    // prologue: panel 0
#pragma unroll
    for (int j = 0; j < 4; j++) {
        int kk = akq + j;
        ra[j]  = (arow < M && kk < ED) ? aptr[kk] : 0.f;
        rbv[j] = (bcol < GW && kk < ED) ? W[(size_t)bcol * ED + kk] : 0.f;
    }
#pragma unroll
    for (int j = 0; j < 4; j++) { As[0][akq + j][am] = ra[j]; Bs[0][akq + j][am] = rbv[j]; }
    __syncthreads();

    for (int p = 0; p < nP; p++) {
        if (p + 1 < nP) {
            int k0 = (p + 1) * 8;
#pragma unroll
            for (int j = 0; j < 4; j++) {
                int kk = k0 + akq + j;
                ra[j]  = (arow < M && kk < ED) ? aptr[kk] : 0.f;
                rbv[j] = (bcol < GW && kk < ED) ? W[(size_t)bcol * ED + kk] : 0.f;
            }
        }
        int b = p & 1;
#pragma unroll
        for (int k = 0; k < 8; k++) {
            float4 a0 = *(const float4*)&As[b][k][ty * 8];
            float4 a1 = *(const float4*)&As[b][k][ty * 8 + 4];
            float4 c0 = *(const float4*)&Bs[b][k][tx * 8];
            float4 c1 = *(const float4*)&Bs[b][k][tx * 8 + 4];
            float av8[8] = {a0.x, a0.y, a0.z, a0.w, a1.x, a1.y, a1.z, a1.w};
            float bv8[8] = {c0.x, c0.y, c0.z, c0.w, c1.x, c1.y, c1.z, c1.w};
#pragma unroll
            for (int i = 0; i < 8; i++)
#pragma unroll
                for (int j = 0; j < 8; j++) acc[i][j] += av8[i] * bv8[j];
        }
        if (p + 1 < nP) {
            int nb = (p + 1) & 1;
#pragma unroll
            for (int j = 0; j < 4; j++) { As[nb][akq + j][am] = ra[j]; Bs[nb][akq + j][am] = rbv[j]; }
            __syncthreads();
        }
    }
#pragma unroll
    for (int i = 0; i < 8; i++) {
        int row = m0 + ty * 8 + i;
        if (row < M) {
#pragma unroll
            for (int j = 0; j < 8; j++) {
                int col = n0 + tx * 8 + j;
                if (col < GW) G[(size_t)row * GW + col] = acc[i][j] + b1[col] + b2[col];
            }
        }
    }
}

// ---------------- generic SGEMM (double-buffered): C = A @ op(B) (+bias)(+tanh) ----
__global__ void __launch_bounds__(256)
gemm_k(const float* __restrict__ A, const float* __restrict__ B,
       const float* __restrict__ bias, float* __restrict__ C,
       int M, int N, int K, int transB, int act) {
    __shared__ __align__(16) float As[2][8][128];
    __shared__ __align__(16) float Bs[2][8][128];
    int tid = threadIdx.x;
    int m0 = blockIdx.y * 128, n0 = blockIdx.x * 128;
    int tx = tid % 16, ty = tid / 16;
    int am = tid >> 1, akq = (tid & 1) * 4;
    int arow = m0 + am, bcol = n0 + am;
    float acc[8][8];
#pragma unroll
    for (int i = 0; i < 8; i++)
#pragma unroll
        for (int j = 0; j < 8; j++) acc[i][j] = 0.f;

    float ra[4], rbv[4];
    const int nP = (K + 7) / 8;

    auto loadP = [&](int k0) {
#pragma unroll
        for (int j = 0; j < 4; j++) {
            int kk = k0 + akq + j;
            ra[j] = (arow < M && kk < K) ? A[(size_t)arow * K + kk] : 0.f;
        }
        if (transB) {
#pragma unroll
            for (int j = 0; j < 4; j++) {
                int kk = k0 + akq + j;
                rbv[j] = (bcol < N && kk < K) ? B[(size_t)bcol * K + kk] : 0.f;
            }
        } else {
#pragma unroll
            for (int i = 0; i < 4; i++) {
                int idx = tid + i * 256;
                int k = idx >> 7, j = idx & 127;
                rbv[i] = (k0 + k < K && n0 + j < N) ? B[(size_t)(k0 + k) * N + n0 + j] : 0.f;
            }
        }
    };
    auto storeP = [&](int b) {
#pragma unroll
        for (int j = 0; j < 4; j++) As[b][akq + j][am] = ra[j];
        if (transB) {
#pragma unroll
            for (int j = 0; j < 4; j++) Bs[b][akq + j][am] = rbv[j];
        } else {
#pragma unroll
            for (int i = 0; i < 4; i++) {
                int idx = tid + i * 256;
                Bs[b][idx >> 7][idx & 127] = rbv[i];
            }
        }
    };

    loadP(0); storeP(0);
    __syncthreads();

    for (int p = 0; p < nP; p++) {
        if (p + 1 < nP) loadP((p + 1) * 8);
        int b = p & 1;
#pragma unroll
        for (int k = 0; k < 8; k++) {
            float4 a0 = *(const float4*)&As[b][k][ty * 8];
            float4 a1 = *(const float4*)&As[b][k][ty * 8 + 4];
            float4 c0 = *(const float4*)&Bs[b][k][tx * 8];
            float4 c1 = *(const float4*)&Bs[b][k][tx * 8 + 4];
            float av8[8] = {a0.x, a0.y, a0.z, a0.w, a1.x, a1.y, a1.z, a1.w};
            float bv8[8] = {c0.x, c0.y, c0.z, c0.w, c1.x, c1.y, c1.z, c1.w};
#pragma unroll
            for (int i = 0; i < 8; i++)
#pragma unroll
                for (int j = 0; j < 8; j++) acc[i][j] += av8[i] * bv8[j];
        }
        if (p + 1 < nP) { storeP((p + 1) & 1); __syncthreads(); }
    }
#pragma unroll
    for (int i = 0; i < 8; i++) {
        int row = m0 + ty * 8 + i;
        if (row < M) {
#pragma unroll
            for (int j = 0; j < 8; j++) {
                int col = n0 + tx * 8 + j;
                if (col < N) {
                    float v = acc[i][j] + (bias ? bias[col] : 0.f);
                    if (act) v = tanhf(v);
                    C[(size_t)row * N + col] = v;
                }
            }
        }
    }
}

// ---------------- fused LSTM recurrence step v3 (one launch per timestep) --------
// grid (10 unit-blocks, 8 row-blocks, 2 dirs) = 160 CTAs x 128 threads.
// CTA = (4 gates x 32 units) x 16 rows. Thread = 4 cols (one gate) x 4 rows:
// per k, 16 FFMA vs 1 LDS.128 + 4 broadcast LDS.32 -> FFMA-bound.
// Warp = single ty => all h_s reads are full-warp broadcasts.
__device__ __forceinline__ float sigm(float x) { return 1.f / (1.f + expf(-x)); }

__global__ void __launch_bounds__(128)
lstm_step(const float* __restrict__ WhhF, const float* __restrict__ WhhB,
          int t, int Lcur, int isq) {
    const int tid = threadIdx.x;
    const int tx = tid & 31;   // col-group: cols tx*4..+3 (within one gate)
    const int ty = tid >> 5;   // 0..3 -> rows ty+4j
    const int ub = blockIdx.x, rbk = blockIdx.y, dir = blockIdx.z;
    const int u0 = ub * 32, n0 = rbk * 16;

    const float* __restrict__ Whh = dir ? WhhB : WhhF;
    const float* __restrict__ G = isq ? (dir ? d_Gqb : d_Gqf)
                                      : (dir ? d_Gb : d_Gf);
    float* hbase = isq ? d_hq : d_h;
    float* cbuf = (isq ? d_cq : d_c) + dir * (NB * HD);
    const float* hp = hbase + (dir * 2 + (t & 1)) * (NB * HD);
    float* hn = hbase + (dir * 2 + ((t + 1) & 1)) * (NB * HD);
    float* Hc = isq ? d_HcatQ : d_Hcat;
    const int tpos = dir ? (Lcur - 1 - t) : t;

    __shared__ __align__(16) float h_s[16][304];  // h_prev rows
    __shared__ __align__(16) float Ws[12][128];   // k-panel of Whh (gate-col major)
    __shared__ __align__(16) float gs[16][128];   // staged gates for cell update

    // stage h_prev rows (16 x 300 = 1200 float4)
    for (int i = tid; i < 16 * 75; i += 128) {
        int r = i / 75, q = i - r * 75;
        float4 v = *((const float4*)(hp + (size_t)(n0 + r) * HD) + q);
        *((float4*)&h_s[r][0] + q) = v;
    }

    // acc init from input-proj gates (biases already included)
    const int gate = tx >> 3;
    const int un = u0 + (tx & 7) * 4;      // unit base of this thread's 4 cols
    const bool uval = (un < HD);           // 4-aligned; HD multiple of 4
    float acc[4][4];
#pragma unroll
    for (int j = 0; j < 4; j++) {
        if (uval) {
            int n = n0 + ty + 4 * j;
            float4 v = *(const float4*)(G + ((size_t)n * Lcur + tpos) * GW
                                          + gate * HD + un);
            acc[j][0] = v.x; acc[j][1] = v.y; acc[j][2] = v.z; acc[j][3] = v.w;
        } else {
            acc[j][0] = acc[j][1] = acc[j][2] = acc[j][3] = 0.f;
        }
    }

    // Whh panel loader: col tid -> gate (tid>>5), unit u0+(tid&31)
    const int lrow = (tid >> 5) * HD + u0 + (tid & 31);
    const bool lval = (u0 + (tid & 31)) < HD;

    for (int k0 = 0; k0 < HD; k0 += 12) {
        __syncthreads();  // WAR on Ws (first iter also covers h_s visibility)
        if (lval) {
            const float* src = Whh + (size_t)lrow * HD + k0;
#pragma unroll
            for (int q = 0; q < 3; q++) {
                float4 v = *((const float4*)src + q);
                Ws[q * 4 + 0][tid] = v.x;
                Ws[q * 4 + 1][tid] = v.y;
                Ws[q * 4 + 2][tid] = v.z;
                Ws[q * 4 + 3][tid] = v.w;
            }
        } else {
#pragma unroll
            for (int kk = 0; kk < 12; kk++) Ws[kk][tid] = 0.f;
        }
        __syncthreads();
#pragma unroll
        for (int kk = 0; kk < 12; kk++) {
            float4 w = *(const float4*)&Ws[kk][tx * 4];
            float h0 = h_s[ty][k0 + kk];
            float h1 = h_s[ty + 4][k0 + kk];
            float h2 = h_s[ty + 8][k0 + kk];
            float h3 = h_s[ty + 12][k0 + kk];
            acc[0][0] += h0 * w.x; acc[0][1] += h0 * w.y;
            acc[0][2] += h0 * w.z; acc[0][3] += h0 * w.w;
            acc[1][0] += h1 * w.x; acc[1][1] += h1 * w.y;
            acc[1][2] += h1 * w.z; acc[1][3] += h1 * w.w;
            acc[2][0] += h2 * w.x; acc[2][1] += h2 * w.y;
            acc[2][2] += h2 * w.z; acc[2][3] += h2 * w.w;
            acc[3][0] += h3 * w.x; acc[3][1] += h3 * w.y;
            acc[3][2] += h3 * w.z; acc[3][3] += h3 * w.w;
        }
    }

    // regroup gates through smem (thread holds 4 cols of ONE gate x 4 rows)
#pragma unroll
    for (int j = 0; j < 4; j++) {
        int r = ty + 4 * j;
        *(float4*)&gs[r][tx * 4] = make_float4(acc[j][0], acc[j][1],
                                               acc[j][2], acc[j][3]);
    }
    __syncthreads();

    // cell update: 4 (unit,row) pairs per thread
    for (int p = tid; p < 512; p += 128) {
        int ulane = p & 31, r = p >> 5;
        int u = u0 + ulane;
        if (u < HD) {
            int n = n0 + r;
            float gi = gs[r][ulane];
            float gf = gs[r][32 + ulane];
            float gg = gs[r][64 + ulane];
            float go = gs[r][96 + ulane];
            float cold = cbuf[n * HD + u];
            float cn = sigm(gf) * cold + sigm(gi) * tanhf(gg);
            float hv = sigm(go) * tanhf(cn);
            cbuf[n * HD + u] = cn;
            hn[n * HD + u] = hv;
            Hc[((size_t)n * Lcur + tpos) * (2 * HD) + dir * HD + u] = hv;
        }
    }
}

// ---------------- attention dot: s[m] = dot(X[m,:], av) ----------------
__global__ void att_dot(const float* __restrict__ X, const float* __restrict__ av,
                        float* __restrict__ out, int M) {
    int w = (blockIdx.x * blockDim.x + threadIdx.x) >> 5;
    int lane = threadIdx.x & 31;
    if (w >= M) return;
    const float* x = X + (size_t)w * HD;
    float a = 0.f;
    for (int d = lane; d < HD; d += 32) a += x[d] * av[d];
#pragma unroll
    for (int o = 16; o; o >>= 1) a += __shfl_down_sync(0xffffffffu, a, o);
    if (lane == 0) out[w] = a;
}

// ---------------- query softmax pool ----------------
__global__ void qpool_k() {
    int n = blockIdx.x, tid = threadIdx.x;  // 128 threads
    __shared__ float sc[QL];
    if (tid < QL) sc[tid] = d_sq[n * QL + tid];
    __syncthreads();
    float mx = -1e30f;
#pragma unroll
    for (int l = 0; l < QL; l++) mx = fmaxf(mx, sc[l]);
    float e[QL], sum = 0.f;
#pragma unroll
    for (int l = 0; l < QL; l++) { e[l] = expf(sc[l] - mx); sum += e[l]; }
    float inv = 1.f / sum;
    for (int d = tid; d < HD; d += 128) {
        float a = 0.f;
#pragma unroll
        for (int l = 0; l < QL; l++) a += e[l] * d_qenc[(n * QL + l) * HD + d];
        d_qv[n * HD + d] = a * inv;
    }
}

// ---------------- normalize query: qn = qp / max(||qp||, eps) ----------------
__global__ void qnorm_k() {
    int n = blockIdx.x, tid = threadIdx.x;  // 128 threads
    __shared__ float red[128];
    float ss = 0.f;
    for (int d = tid; d < HD; d += 128) { float v = d_qp[n * HD + d]; ss += v * v; }
    red[tid] = ss;
    __syncthreads();
    for (int s = 64; s; s >>= 1) { if (tid < s) red[tid] += red[tid + s]; __syncthreads(); }
    float inv = 1.f / fmaxf(sqrtf(red[0]), EPSN);
    for (int d = tid; d < HD; d += 128) d_qn[n * HD + d] = d_qp[n * HD + d] * inv;
}

// ---------------- final: sliding-window combos + cosines + mix ----------------
__global__ void final_k(const float* __restrict__ sw, const float* __restrict__ P,
                        float* __restrict__ out) {
    int w = (blockIdx.x * blockDim.x + threadIdx.x) >> 5;
    int lane = threadIdx.x & 31;
    if (w >= MS) return;
    int n = w >> 8, l = w & 255;
    int ln = (l + 1 < SL) ? l + 1 : SL - 1;
    int lp = (l > 0) ? l - 1 : 0;
    float sl = d_s[n * SL + l];
    float sn = d_s[n * SL + ln];
    float sp = d_s[n * SL + lp];
    float m1 = fmaxf(sl, sn);
    float e0 = expf(sl - m1), e1 = expf(sn - m1);
    float wf0 = e0 / (e0 + e1), wf1 = 1.f - wf0;
    float m2 = fmaxf(sp, sl);
    float f0 = expf(sp - m2), f1 = expf(sl - m2);
    float wb0 = f0 / (f0 + f1), wb1 = 1.f - wb0;

    const float* Pl = P + (size_t)(n * SL + l) * HD;
    const float* Pn = P + (size_t)(n * SL + ln) * HD;
    const float* Pp = P + (size_t)(n * SL + lp) * HD;
    const float* q = d_qn + n * HD;

    float dpq = 0.f, dpp = 0.f, duq = 0.f, duu = 0.f, dvq = 0.f, dvv = 0.f;
    for (int d = lane; d < HD; d += 32) {
        float p = Pl[d], pn = Pn[d], pp = Pp[d], qd = q[d];
        float u = wf0 * p + wf1 * pn;
        float v = wb0 * pp + wb1 * p;
        dpq += p * qd; dpp += p * p;
        duq += u * qd; duu += u * u;
        dvq += v * qd; dvv += v * v;
    }
#pragma unroll
    for (int o = 16; o; o >>= 1) {
        dpq += __shfl_down_sync(0xffffffffu, dpq, o);
        dpp += __shfl_down_sync(0xffffffffu, dpp, o);
        duq += __shfl_down_sync(0xffffffffu, duq, o);
        duu += __shfl_down_sync(0xffffffffu, duu, o);
        dvq += __shfl_down_sync(0xffffffffu, dvq, o);
        dvv += __shfl_down_sync(0xffffffffu, dvv, o);
    }
    if (lane == 0) {
        float c1 = dpq / fmaxf(sqrtf(dpp), EPSN);
        float c2 = duq / fmaxf(sqrtf(duu), EPSN);
        float c3 = dvq / fmaxf(sqrtf(dvv), EPSN);
        out[w] = c1 * sw[0] + c2 * sw[1] + c3 * sw[2];
    }
}

// ---------------- launch ----------------
extern "C" void kernel_launch(void* const* d_in, const int* in_sizes, int n_in,
                              void* d_out, int out_size) {
    const int*   seqs = (const int*)d_in[0];
    const int*   quer = (const int*)d_in[1];
    const float* emb  = (const float*)d_in[2];
    const float* WihF = (const float*)d_in[3];
    const float* WhhF = (const float*)d_in[4];
    const float* bihF = (const float*)d_in[5];
    const float* bhhF = (const float*)d_in[6];
    const float* WihB = (const float*)d_in[7];
    const float* WhhB = (const float*)d_in[8];
    const float* bihB = (const float*)d_in[9];
    const float* bhhB = (const float*)d_in[10];
    const float* Wc   = (const float*)d_in[11];
    const float* bc   = (const float*)d_in[12];
    const float* Wa   = (const float*)d_in[13];
    const float* ba   = (const float*)d_in[14];
    const float* av   = (const float*)d_in[15];
    const float* Wf   = (const float*)d_in[16];
    const float* sw   = (const float*)d_in[17];

    void* p;
    cudaGetSymbolAddress(&p, d_Gf);    float* pGf    = (float*)p;
    cudaGetSymbolAddress(&p, d_Gb);    float* pGb    = (float*)p;
    cudaGetSymbolAddress(&p, d_Gqf);   float* pGqf   = (float*)p;
    cudaGetSymbolAddress(&p, d_Gqb);   float* pGqb   = (float*)p;
    cudaGetSymbolAddress(&p, d_Hcat);  float* pHcat  = (float*)p;
    cudaGetSymbolAddress(&p, d_HcatQ); float* pHcatQ = (float*)p;
    cudaGetSymbolAddress(&p, d_hs);    float* phs    = (float*)p;
    cudaGetSymbolAddress(&p, d_qenc);  float* pqenc  = (float*)p;
    cudaGetSymbolAddress(&p, d_tmp);   float* ptmp   = (float*)p;  // doubles as P
    cudaGetSymbolAddress(&p, d_tmpq);  float* ptmpq  = (float*)p;
    cudaGetSymbolAddress(&p, d_s);     float* ps     = (float*)p;
    cudaGetSymbolAddress(&p, d_sq);    float* psq    = (float*)p;
    cudaGetSymbolAddress(&p, d_qv);    float* pqv    = (float*)p;
    cudaGetSymbolAddress(&p, d_qp);    float* pqp    = (float*)p;

    init_state<<<600, 256>>>();

    // input projections (gather + GEMM + both biases)
    dim3 gp(10, 256);
    proj_gemm<<<gp, 256>>>(seqs, emb, WihF, bihF, bhhF, pGf, MS);
    proj_gemm<<<gp, 256>>>(seqs, emb, WihB, bihB, bhhB, pGb, MS);
    dim3 gpq(10, 8);
    proj_gemm<<<gpq, 256>>>(quer, emb, WihF, bihF, bhhF, pGqf, MQ);
    proj_gemm<<<gpq, 256>>>(quer, emb, WihB, bihB, bhhB, pGqb, MQ);

    // recurrences: one launch per timestep, both dirs (proven-safe structure)
    dim3 gl(10, 8, 2);
    for (int t = 0; t < SL; t++) lstm_step<<<gl, 128>>>(WhhF, WhhB, t, SL, 0);
    for (int t = 0; t < QL; t++) lstm_step<<<gl, 128>>>(WhhF, WhhB, t, QL, 1);

    // combine directions: hs = Hcat @ Wc^T + bc
    gemm_k<<<dim3(3, 256), 256>>>(pHcat, Wc, bc, phs, MS, HD, 2 * HD, 1, 0);
    gemm_k<<<dim3(3, 8), 256>>>(pHcatQ, Wc, bc, pqenc, MQ, HD, 2 * HD, 1, 0);

    // attention logits: tanh(X @ Wa^T + ba) . att_vec
    gemm_k<<<dim3(3, 256), 256>>>(phs, Wa, ba, ptmp, MS, HD, HD, 1, 1);
    gemm_k<<<dim3(3, 8), 256>>>(pqenc, Wa, ba, ptmpq, MQ, HD, HD, 1, 1);
    att_dot<<<MS / 8, 256>>>(ptmp, av, ps, MS);
    att_dot<<<MQ / 8, 256>>>(ptmpq, av, psq, MQ);

    // pooled, projected, normalized query
    qpool_k<<<NB, 128>>>();
    gemm_k<<<dim3(3, 1), 256>>>(pqv, Wf, nullptr, pqp, NB, HD, HD, 0, 0);
    qnorm_k<<<NB, 128>>>();

    // P = hs @ Wf  (fwd/bwd combos are linear in hs, so one projection suffices)
    gemm_k<<<dim3(3, 256), 256>>>(phs, Wf, nullptr, ptmp, MS, HD, HD, 0, 0);

    final_k<<<MS / 8, 256>>>(sw, ptmp, (float*)d_out);
}

// round 7
// speedup vs baseline: 2.1014x; 1.2848x over previous
#include <cuda_runtime.h>
#include <math.h>

static constexpr int NB = 128;     // batch
static constexpr int SL = 256;     // seq len
static constexpr int QL = 8;       // query len
static constexpr int ED = 300;     // embed dim
static constexpr int HD = 300;     // hidden dim
static constexpr int GW = 1200;    // 4*HD gate width
static constexpr int MS = NB * SL; // 32768
static constexpr int MQ = NB * QL; // 1024
static constexpr float EPSN = 1e-12f;

// ---------------- static device scratch (no runtime allocation) ----------------
__device__ float d_Gf[MS * GW];        // input-proj gates, seqs forward  (incl. biases)
__device__ float d_Gb[MS * GW];        // seqs backward
__device__ float d_Gqf[MQ * GW];       // queries forward
__device__ float d_Gqb[MQ * GW];       // queries backward
__device__ float d_Hcat[MS * 2 * HD];  // [N, L, 2H] concat(hf, hb)
__device__ float d_HcatQ[MQ * 2 * HD];
__device__ float d_h[2 * 2 * NB * HD]; // [dir][parity][N*H] ping-pong hidden
__device__ float d_c[2 * NB * HD];     // [dir][N*H] cell (seqs)
__device__ float d_hq[2 * 2 * NB * HD];
__device__ float d_cq[2 * NB * HD];    // cell (queries)
__device__ float d_hs[MS * HD];        // encoded seq states
__device__ float d_qenc[MQ * HD];      // encoded query states
__device__ float d_tmp[MS * HD];       // tanh(hs@Wa^T+ba); later reused as P = hs@Wf
__device__ float d_tmpq[MQ * HD];
__device__ float d_s[MS];              // attention logits (seqs)
__device__ float d_sq[MQ];             // attention logits (queries)
__device__ float d_qv[NB * HD];        // pooled query vec
__device__ float d_qp[NB * HD];        // qv @ Wf
__device__ float d_qn[NB * HD];        // normalized

// ---------------- init ----------------
__global__ void init_state() {
    int i = blockIdx.x * blockDim.x + threadIdx.x;
    if (i < 2 * 2 * NB * HD) { d_h[i] = 0.f; d_hq[i] = 0.f; }
    if (i < 2 * NB * HD)     { d_c[i] = 0.f; d_cq[i] = 0.f; }
}

// ---------------- gathered input-projection GEMM (double-buffered) ----------------
// G[m, j] = sum_e emb[tok[m], e] * W[j, e] + b1[j] + b2[j]    (M x 1200, K=300)
__global__ void __launch_bounds__(256)
proj_gemm(const int* __restrict__ tok, const float* __restrict__ emb,
          const float* __restrict__ W, const float* __restrict__ b1,
          const float* __restrict__ b2, float* __restrict__ G, int M) {
    __shared__ __align__(16) float As[2][8][128];
    __shared__ __align__(16) float Bs[2][8][128];
    int tid = threadIdx.x;
    int m0 = blockIdx.y * 128, n0 = blockIdx.x * 128;
    int tx = tid % 16, ty = tid / 16;
    int am = tid >> 1, akq = (tid & 1) * 4;
    int arow = m0 + am;
    const float* aptr = emb + (size_t)((arow < M) ? tok[arow] : 0) * ED;
    int bcol = n0 + am;
    float acc[8][8];
#pragma unroll
    for (int i = 0; i < 8; i++)
#pragma unroll
        for (int j = 0; j < 8; j++) acc[i][j] = 0.f;

    float ra[4], rbv[4];
    const int nP = (ED + 7) / 8;  // 38

#pragma unroll
    for (int j = 0; j < 4; j++) {
        int kk = akq + j;
        ra[j]  = (arow < M && kk < ED) ? aptr[kk] : 0.f;
        rbv[j] = (bcol < GW && kk < ED) ? W[(size_t)bcol * ED + kk] : 0.f;
    }
#pragma unroll
    for (int j = 0; j < 4; j++) { As[0][akq + j][am] = ra[j]; Bs[0][akq + j][am] = rbv[j]; }
    __syncthreads();

    for (int p = 0; p < nP; p++) {
        if (p + 1 < nP) {
            int k0 = (p + 1) * 8;
#pragma unroll
            for (int j = 0; j < 4; j++) {
                int kk = k0 + akq + j;
                ra[j]  = (arow < M && kk < ED) ? aptr[kk] : 0.f;
                rbv[j] = (bcol < GW && kk < ED) ? W[(size_t)bcol * ED + kk] : 0.f;
            }
        }
        int b = p & 1;
#pragma unroll
        for (int k = 0; k < 8; k++) {
            float4 a0 = *(const float4*)&As[b][k][ty * 8];
            float4 a1 = *(const float4*)&As[b][k][ty * 8 + 4];
            float4 c0 = *(const float4*)&Bs[b][k][tx * 8];
            float4 c1 = *(const float4*)&Bs[b][k][tx * 8 + 4];
            float av8[8] = {a0.x, a0.y, a0.z, a0.w, a1.x, a1.y, a1.z, a1.w};
            float bv8[8] = {c0.x, c0.y, c0.z, c0.w, c1.x, c1.y, c1.z, c1.w};
#pragma unroll
            for (int i = 0; i < 8; i++)
#pragma unroll
                for (int j = 0; j < 8; j++) acc[i][j] += av8[i] * bv8[j];
        }
        if (p + 1 < nP) {
            int nb = (p + 1) & 1;
#pragma unroll
            for (int j = 0; j < 4; j++) { As[nb][akq + j][am] = ra[j]; Bs[nb][akq + j][am] = rbv[j]; }
            __syncthreads();
        }
    }
#pragma unroll
    for (int i = 0; i < 8; i++) {
        int row = m0 + ty * 8 + i;
        if (row < M) {
#pragma unroll
            for (int j = 0; j < 8; j++) {
                int col = n0 + tx * 8 + j;
                if (col < GW) G[(size_t)row * GW + col] = acc[i][j] + b1[col] + b2[col];
            }
        }
    }
}

// ---------------- generic SGEMM (double-buffered): C = A @ op(B) (+bias)(+tanh) ----
__global__ void __launch_bounds__(256)
gemm_k(const float* __restrict__ A, const float* __restrict__ B,
       const float* __restrict__ bias, float* __restrict__ C,
       int M, int N, int K, int transB, int act) {
    __shared__ __align__(16) float As[2][8][128];
    __shared__ __align__(16) float Bs[2][8][128];
    int tid = threadIdx.x;
    int m0 = blockIdx.y * 128, n0 = blockIdx.x * 128;
    int tx = tid % 16, ty = tid / 16;
    int am = tid >> 1, akq = (tid & 1) * 4;
    int arow = m0 + am, bcol = n0 + am;
    float acc[8][8];
#pragma unroll
    for (int i = 0; i < 8; i++)
#pragma unroll
        for (int j = 0; j < 8; j++) acc[i][j] = 0.f;

    float ra[4], rbv[4];
    const int nP = (K + 7) / 8;

    auto loadP = [&](int k0) {
#pragma unroll
        for (int j = 0; j < 4; j++) {
            int kk = k0 + akq + j;
            ra[j] = (arow < M && kk < K) ? A[(size_t)arow * K + kk] : 0.f;
        }
        if (transB) {
#pragma unroll
            for (int j = 0; j < 4; j++) {
                int kk = k0 + akq + j;
                rbv[j] = (bcol < N && kk < K) ? B[(size_t)bcol * K + kk] : 0.f;
            }
        } else {
#pragma unroll
            for (int i = 0; i < 4; i++) {
                int idx = tid + i * 256;
                int k = idx >> 7, j = idx & 127;
                rbv[i] = (k0 + k < K && n0 + j < N) ? B[(size_t)(k0 + k) * N + n0 + j] : 0.f;
            }
        }
    };
    auto storeP = [&](int b) {
#pragma unroll
        for (int j = 0; j < 4; j++) As[b][akq + j][am] = ra[j];
        if (transB) {
#pragma unroll
            for (int j = 0; j < 4; j++) Bs[b][akq + j][am] = rbv[j];
        } else {
#pragma unroll
            for (int i = 0; i < 4; i++) {
                int idx = tid + i * 256;
                Bs[b][idx >> 7][idx & 127] = rbv[i];
            }
        }
    };

    loadP(0); storeP(0);
    __syncthreads();

    for (int p = 0; p < nP; p++) {
        if (p + 1 < nP) loadP((p + 1) * 8);
        int b = p & 1;
#pragma unroll
        for (int k = 0; k < 8; k++) {
            float4 a0 = *(const float4*)&As[b][k][ty * 8];
            float4 a1 = *(const float4*)&As[b][k][ty * 8 + 4];
            float4 c0 = *(const float4*)&Bs[b][k][tx * 8];
            float4 c1 = *(const float4*)&Bs[b][k][tx * 8 + 4];
            float av8[8] = {a0.x, a0.y, a0.z, a0.w, a1.x, a1.y, a1.z, a1.w};
            float bv8[8] = {c0.x, c0.y, c0.z, c0.w, c1.x, c1.y, c1.z, c1.w};
#pragma unroll
            for (int i = 0; i < 8; i++)
#pragma unroll
                for (int j = 0; j < 8; j++) acc[i][j] += av8[i] * bv8[j];
        }
        if (p + 1 < nP) { storeP((p + 1) & 1); __syncthreads(); }
    }
#pragma unroll
    for (int i = 0; i < 8; i++) {
        int row = m0 + ty * 8 + i;
        if (row < M) {
#pragma unroll
            for (int j = 0; j < 8; j++) {
                int col = n0 + tx * 8 + j;
                if (col < N) {
                    float v = acc[i][j] + (bias ? bias[col] : 0.f);
                    if (act) v = tanhf(v);
                    C[(size_t)row * N + col] = v;
                }
            }
        }
    }
}

// ---------------- fused LSTM recurrence step v4 (double-buffered weights) --------
// grid (10, 8, 2) = 160 CTAs x 128 threads. CTA = (4 gates x 32 units) x 16 rows.
// Thread = 4 cols (one gate) x 4 rows -> 16 FFMA per k.
// Whh streamed in 20-k panels, double-buffered with register prefetch:
// compute(panel p) overlaps LDG(panel p+1); one __syncthreads per panel.
__device__ __forceinline__ float sigm(float x) { return 1.f / (1.f + expf(-x)); }

__global__ void __launch_bounds__(128)
lstm_step(const float* __restrict__ WhhF, const float* __restrict__ WhhB,
          int t, int Lcur, int isq) {
    const int tid = threadIdx.x;
    const int tx = tid & 31;   // col-group: cols tx*4..+3 (gate = tx>>3)
    const int ty = tid >> 5;   // 0..3 -> rows ty+4j
    const int ub = blockIdx.x, rbk = blockIdx.y, dir = blockIdx.z;
    const int u0 = ub * 32, n0 = rbk * 16;

    const float* __restrict__ Whh = dir ? WhhB : WhhF;
    const float* __restrict__ G = isq ? (dir ? d_Gqb : d_Gqf)
                                      : (dir ? d_Gb : d_Gf);
    float* hbase = isq ? d_hq : d_h;
    float* cbuf = (isq ? d_cq : d_c) + dir * (NB * HD);
    const float* hp = hbase + (dir * 2 + (t & 1)) * (NB * HD);
    float* hn = hbase + (dir * 2 + ((t + 1) & 1)) * (NB * HD);
    float* Hc = isq ? d_HcatQ : d_Hcat;
    const int tpos = dir ? (Lcur - 1 - t) : t;

    __shared__ __align__(16) float h_s[16][304];     // h_prev rows
    __shared__ __align__(16) float Ws[2][20][128];   // double-buffered k-panels
    __shared__ __align__(16) float gs[16][128];      // staged gates

    // --- issue acc-init gate loads first (independent global traffic) ---
    const int gate = tx >> 3;
    const int un = u0 + (tx & 7) * 4;
    const bool uval = (un < HD);
    float acc[4][4];
#pragma unroll
    for (int j = 0; j < 4; j++) {
        if (uval) {
            int n = n0 + ty + 4 * j;
            float4 v = *(const float4*)(G + ((size_t)n * Lcur + tpos) * GW
                                          + gate * HD + un);
            acc[j][0] = v.x; acc[j][1] = v.y; acc[j][2] = v.z; acc[j][3] = v.w;
        } else {
            acc[j][0] = acc[j][1] = acc[j][2] = acc[j][3] = 0.f;
        }
    }

    // --- h_prev staging: LDG phase (full MLP) then STS phase ---
    float4 hreg[10];
#pragma unroll
    for (int q = 0; q < 10; q++) {
        int i = tid + q * 128;
        if (i < 1200) {
            int r = i / 75, c = i - r * 75;
            hreg[q] = *((const float4*)(hp + (size_t)(n0 + r) * HD) + c);
        }
    }
#pragma unroll
    for (int q = 0; q < 10; q++) {
        int i = tid + q * 128;
        if (i < 1200) {
            int r = i / 75, c = i - r * 75;
            *((float4*)&h_s[r][0] + c) = hreg[q];
        }
    }

    // --- Whh panel pipeline (20 k per panel, 15 panels) ---
    const int lrow = (tid >> 5) * HD + u0 + (tid & 31);
    const bool lval = (u0 + (tid & 31)) < HD;
    float4 pre[5];

    // prologue: panel 0
    if (lval) {
        const float* src = Whh + (size_t)lrow * HD;
#pragma unroll
        for (int q = 0; q < 5; q++) pre[q] = ((const float4*)src)[q];
    }
    if (lval) {
#pragma unroll
        for (int q = 0; q < 5; q++) {
            Ws[0][q * 4 + 0][tid] = pre[q].x;
            Ws[0][q * 4 + 1][tid] = pre[q].y;
            Ws[0][q * 4 + 2][tid] = pre[q].z;
            Ws[0][q * 4 + 3][tid] = pre[q].w;
        }
    } else {
#pragma unroll
        for (int kk = 0; kk < 20; kk++) Ws[0][kk][tid] = 0.f;
    }
    __syncthreads();  // panel 0 + h_s visible

    for (int p = 0; p < 15; p++) {
        if (p + 1 < 15) {
            if (lval) {
                const float* src = Whh + (size_t)lrow * HD + (p + 1) * 20;
#pragma unroll
                for (int q = 0; q < 5; q++) pre[q] = ((const float4*)src)[q];
            }
        }
        const int b = p & 1, k0 = p * 20;
#pragma unroll
        for (int kk = 0; kk < 20; kk++) {
            float4 w = *(const float4*)&Ws[b][kk][tx * 4];
            float h0 = h_s[ty][k0 + kk];
            float h1 = h_s[ty + 4][k0 + kk];
            float h2 = h_s[ty + 8][k0 + kk];
            float h3 = h_s[ty + 12][k0 + kk];
            acc[0][0] += h0 * w.x; acc[0][1] += h0 * w.y;
            acc[0][2] += h0 * w.z; acc[0][3] += h0 * w.w;
            acc[1][0] += h1 * w.x; acc[1][1] += h1 * w.y;
            acc[1][2] += h1 * w.z; acc[1][3] += h1 * w.w;
            acc[2][0] += h2 * w.x; acc[2][1] += h2 * w.y;
            acc[2][2] += h2 * w.z; acc[2][3] += h2 * w.w;
            acc[3][0] += h3 * w.x; acc[3][1] += h3 * w.y;
            acc[3][2] += h3 * w.z; acc[3][3] += h3 * w.w;
        }
        if (p + 1 < 15) {
            const int nb = (p + 1) & 1;
            if (lval) {
#pragma unroll
                for (int q = 0; q < 5; q++) {
                    Ws[nb][q * 4 + 0][tid] = pre[q].x;
                    Ws[nb][q * 4 + 1][tid] = pre[q].y;
                    Ws[nb][q * 4 + 2][tid] = pre[q].z;
                    Ws[nb][q * 4 + 3][tid] = pre[q].w;
                }
            } else {
#pragma unroll
                for (int kk = 0; kk < 20; kk++) Ws[nb][kk][tid] = 0.f;
            }
            __syncthreads();
        }
    }

    // regroup gates through smem (thread holds 4 cols of ONE gate x 4 rows)
#pragma unroll
    for (int j = 0; j < 4; j++) {
        int r = ty + 4 * j;
        *(float4*)&gs[r][tx * 4] = make_float4(acc[j][0], acc[j][1],
                                               acc[j][2], acc[j][3]);
    }
    __syncthreads();

    // cell update: 4 (unit,row) pairs per thread
    for (int p = tid; p < 512; p += 128) {
        int ulane = p & 31, r = p >> 5;
        int u = u0 + ulane;
        if (u < HD) {
            int n = n0 + r;
            float gi = gs[r][ulane];
            float gf = gs[r][32 + ulane];
            float gg = gs[r][64 + ulane];
            float go = gs[r][96 + ulane];
            float cold = cbuf[n * HD + u];
            float cn = sigm(gf) * cold + sigm(gi) * tanhf(gg);
            float hv = sigm(go) * tanhf(cn);
            cbuf[n * HD + u] = cn;
            hn[n * HD + u] = hv;
            Hc[((size_t)n * Lcur + tpos) * (2 * HD) + dir * HD + u] = hv;
        }
    }
}

// ---------------- attention dot: s[m] = dot(X[m,:], av) ----------------
__global__ void att_dot(const float* __restrict__ X, const float* __restrict__ av,
                        float* __restrict__ out, int M) {
    int w = (blockIdx.x * blockDim.x + threadIdx.x) >> 5;
    int lane = threadIdx.x & 31;
    if (w >= M) return;
    const float* x = X + (size_t)w * HD;
    float a = 0.f;
    for (int d = lane; d < HD; d += 32) a += x[d] * av[d];
#pragma unroll
    for (int o = 16; o; o >>= 1) a += __shfl_down_sync(0xffffffffu, a, o);
    if (lane == 0) out[w] = a;
}

// ---------------- query softmax pool ----------------
__global__ void qpool_k() {
    int n = blockIdx.x, tid = threadIdx.x;  // 128 threads
    __shared__ float sc[QL];
    if (tid < QL) sc[tid] = d_sq[n * QL + tid];
    __syncthreads();
    float mx = -1e30f;
#pragma unroll
    for (int l = 0; l < QL; l++) mx = fmaxf(mx, sc[l]);
    float e[QL], sum = 0.f;
#pragma unroll
    for (int l = 0; l < QL; l++) { e[l] = expf(sc[l] - mx); sum += e[l]; }
    float inv = 1.f / sum;
    for (int d = tid; d < HD; d += 128) {
        float a = 0.f;
#pragma unroll
        for (int l = 0; l < QL; l++) a += e[l] * d_qenc[(n * QL + l) * HD + d];
        d_qv[n * HD + d] = a * inv;
    }
}

// ---------------- normalize query: qn = qp / max(||qp||, eps) ----------------
__global__ void qnorm_k() {
    int n = blockIdx.x, tid = threadIdx.x;  // 128 threads
    __shared__ float red[128];
    float ss = 0.f;
    for (int d = tid; d < HD; d += 128) { float v = d_qp[n * HD + d]; ss += v * v; }
    red[tid] = ss;
    __syncthreads();
    for (int s = 64; s; s >>= 1) { if (tid < s) red[tid] += red[tid + s]; __syncthreads(); }
    float inv = 1.f / fmaxf(sqrtf(red[0]), EPSN);
    for (int d = tid; d < HD; d += 128) d_qn[n * HD + d] = d_qp[n * HD + d] * inv;
}

// ---------------- final: sliding-window combos + cosines + mix ----------------
__global__ void final_k(const float* __restrict__ sw, const float* __restrict__ P,
                        float* __restrict__ out) {
    int w = (blockIdx.x * blockDim.x + threadIdx.x) >> 5;
    int lane = threadIdx.x & 31;
    if (w >= MS) return;
    int n = w >> 8, l = w & 255;
    int ln = (l + 1 < SL) ? l + 1 : SL - 1;
    int lp = (l > 0) ? l - 1 : 0;
    float sl = d_s[n * SL + l];
    float sn = d_s[n * SL + ln];
    float sp = d_s[n * SL + lp];
    float m1 = fmaxf(sl, sn);
    float e0 = expf(sl - m1), e1 = expf(sn - m1);
    float wf0 = e0 / (e0 + e1), wf1 = 1.f - wf0;
    float m2 = fmaxf(sp, sl);
    float f0 = expf(sp - m2), f1 = expf(sl - m2);
    float wb0 = f0 / (f0 + f1), wb1 = 1.f - wb0;

    const float* Pl = P + (size_t)(n * SL + l) * HD;
    const float* Pn = P + (size_t)(n * SL + ln) * HD;
    const float* Pp = P + (size_t)(n * SL + lp) * HD;
    const float* q = d_qn + n * HD;

    float dpq = 0.f, dpp = 0.f, duq = 0.f, duu = 0.f, dvq = 0.f, dvv = 0.f;
    for (int d = lane; d < HD; d += 32) {
        float p = Pl[d], pn = Pn[d], pp = Pp[d], qd = q[d];
        float u = wf0 * p + wf1 * pn;
        float v = wb0 * pp + wb1 * p;
        dpq += p * qd; dpp += p * p;
        duq += u * qd; duu += u * u;
        dvq += v * qd; dvv += v * v;
    }
#pragma unroll
    for (int o = 16; o; o >>= 1) {
        dpq += __shfl_down_sync(0xffffffffu, dpq, o);
        dpp += __shfl_down_sync(0xffffffffu, dpp, o);
        duq += __shfl_down_sync(0xffffffffu, duq, o);
        duu += __shfl_down_sync(0xffffffffu, duu, o);
        dvq += __shfl_down_sync(0xffffffffu, dvq, o);
        dvv += __shfl_down_sync(0xffffffffu, dvv, o);
    }
    if (lane == 0) {
        float c1 = dpq / fmaxf(sqrtf(dpp), EPSN);
        float c2 = duq / fmaxf(sqrtf(duu), EPSN);
        float c3 = dvq / fmaxf(sqrtf(dvv), EPSN);
        out[w] = c1 * sw[0] + c2 * sw[1] + c3 * sw[2];
    }
}

// ---------------- launch ----------------
extern "C" void kernel_launch(void* const* d_in, const int* in_sizes, int n_in,
                              void* d_out, int out_size) {
    const int*   seqs = (const int*)d_in[0];
    const int*   quer = (const int*)d_in[1];
    const float* emb  = (const float*)d_in[2];
    const float* WihF = (const float*)d_in[3];
    const float* WhhF = (const float*)d_in[4];
    const float* bihF = (const float*)d_in[5];
    const float* bhhF = (const float*)d_in[6];
    const float* WihB = (const float*)d_in[7];
    const float* WhhB = (const float*)d_in[8];
    const float* bihB = (const float*)d_in[9];
    const float* bhhB = (const float*)d_in[10];
    const float* Wc   = (const float*)d_in[11];
    const float* bc   = (const float*)d_in[12];
    const float* Wa   = (const float*)d_in[13];
    const float* ba   = (const float*)d_in[14];
    const float* av   = (const float*)d_in[15];
    const float* Wf   = (const float*)d_in[16];
    const float* sw   = (const float*)d_in[17];

    void* p;
    cudaGetSymbolAddress(&p, d_Gf);    float* pGf    = (float*)p;
    cudaGetSymbolAddress(&p, d_Gb);    float* pGb    = (float*)p;
    cudaGetSymbolAddress(&p, d_Gqf);   float* pGqf   = (float*)p;
    cudaGetSymbolAddress(&p, d_Gqb);   float* pGqb   = (float*)p;
    cudaGetSymbolAddress(&p, d_Hcat);  float* pHcat  = (float*)p;
    cudaGetSymbolAddress(&p, d_HcatQ); float* pHcatQ = (float*)p;
    cudaGetSymbolAddress(&p, d_hs);    float* phs    = (float*)p;
    cudaGetSymbolAddress(&p, d_qenc);  float* pqenc  = (float*)p;
    cudaGetSymbolAddress(&p, d_tmp);   float* ptmp   = (float*)p;  // doubles as P
    cudaGetSymbolAddress(&p, d_tmpq);  float* ptmpq  = (float*)p;
    cudaGetSymbolAddress(&p, d_s);     float* ps     = (float*)p;
    cudaGetSymbolAddress(&p, d_sq);    float* psq    = (float*)p;
    cudaGetSymbolAddress(&p, d_qv);    float* pqv    = (float*)p;
    cudaGetSymbolAddress(&p, d_qp);    float* pqp    = (float*)p;

    init_state<<<600, 256>>>();

    // input projections (gather + GEMM + both biases)
    dim3 gp(10, 256);
    proj_gemm<<<gp, 256>>>(seqs, emb, WihF, bihF, bhhF, pGf, MS);
    proj_gemm<<<gp, 256>>>(seqs, emb, WihB, bihB, bhhB, pGb, MS);
    dim3 gpq(10, 8);
    proj_gemm<<<gpq, 256>>>(quer, emb, WihF, bihF, bhhF, pGqf, MQ);
    proj_gemm<<<gpq, 256>>>(quer, emb, WihB, bihB, bhhB, pGqb, MQ);

    // recurrences: one launch per timestep, both dirs (proven-safe structure)
    dim3 gl(10, 8, 2);
    for (int t = 0; t < SL; t++) lstm_step<<<gl, 128>>>(WhhF, WhhB, t, SL, 0);
    for (int t = 0; t < QL; t++) lstm_step<<<gl, 128>>>(WhhF, WhhB, t, QL, 1);

    // combine directions: hs = Hcat @ Wc^T + bc
    gemm_k<<<dim3(3, 256), 256>>>(pHcat, Wc, bc, phs, MS, HD, 2 * HD, 1, 0);
    gemm_k<<<dim3(3, 8), 256>>>(pHcatQ, Wc, bc, pqenc, MQ, HD, 2 * HD, 1, 0);

    // attention logits: tanh(X @ Wa^T + ba) . att_vec
    gemm_k<<<dim3(3, 256), 256>>>(phs, Wa, ba, ptmp, MS, HD, HD, 1, 1);
    gemm_k<<<dim3(3, 8), 256>>>(pqenc, Wa, ba, ptmpq, MQ, HD, HD, 1, 1);
    att_dot<<<MS / 8, 256>>>(ptmp, av, ps, MS);
    att_dot<<<MQ / 8, 256>>>(ptmpq, av, psq, MQ);

    // pooled, projected, normalized query
    qpool_k<<<NB, 128>>>();
    gemm_k<<<dim3(3, 1), 256>>>(pqv, Wf, nullptr, pqp, NB, HD, HD, 0, 0);
    qnorm_k<<<NB, 128>>>();

    // P = hs @ Wf  (fwd/bwd combos are linear in hs, so one projection suffices)
    gemm_k<<<dim3(3, 256), 256>>>(phs, Wf, nullptr, ptmp, MS, HD, HD, 0, 0);

    final_k<<<MS / 8, 256>>>(sw, ptmp, (float*)d_out);
}